// round 6
// baseline (speedup 1.0000x reference)
#include <cuda_runtime.h>

// tanhP1 bitstream stencil — R3 chunked structure + scalar columns.
// out[t] = n5 * x[t-8]:
//   n1 = x[t]*x[t-4]
//   n2 = 1 - n1*c2[t]
//   n3 = 1 - n2*c3[t]*n1[t-1]
//   n4 = 1 - n3*c4[t]*n1[t-2]
//   n5 = 1 - n4*c5[t]*n1[t-3]
// Exact {0,1} floats -> FFMA arithmetic is bit-exact.
//
// Round-6 rationale:
//  * t-chunking (CH=64, 4 concurrent chunks) is what sustained 6.11 TB/s in
//    R3 — multiple decorrelated DRAM streams + staggered waves. Full-T
//    single-wave variants (R4/R5) sat at 5.55 TB/s regardless of occupancy.
//  * scalar columns -> 4096 blocks / 32 regs: more blocks & waves along the
//    proven axis; R5 showed scalar vs float2 itself is neutral.
//  * no streaming hints: halo rows (chunk tails) want L2 retention, and the
//    hints coincided with the R4 BW regression.

#define TT 256
#define CH 64          // chunk length (multiple of 8)

__global__ __launch_bounds__(256)
void tanhP1_kernel(const float* __restrict__ x,
                   const float* __restrict__ c2,
                   const float* __restrict__ c3,
                   const float* __restrict__ c4,
                   const float* __restrict__ c5,
                   float* __restrict__ out,
                   int n)    // N columns
{
    __shared__ float4 cc[TT];
    for (int i = threadIdx.x; i < TT; i += blockDim.x)
        cc[i] = make_float4(c2[i], c3[i], c4[i], c5[i]);
    __syncthreads();

    const int col = blockIdx.x * blockDim.x + threadIdx.x;
    if (col >= n) return;
    const int t0 = blockIdx.y * CH;          // multiple of 8

    const float* xp = x + col;
    float*       op = out + col;

    // Delay lines: x at time s lives in slot s&7; n1 at time s in slot s&3.
    float xh[8];
    float nh[4];

    if (t0 == 0) {
#pragma unroll
        for (int i = 0; i < 8; i++) xh[i] = 0.0f;
#pragma unroll
        for (int i = 0; i < 4; i++) nh[i] = 0.0f;
    } else {
        // Halo rows t0-8..t0-1 land in slots 0..7 (t0 % 8 == 0).
#pragma unroll
        for (int k = 0; k < 8; k++)
            xh[k] = xp[(long)(t0 - 8 + k) * n];
        // n1[s] = x[s]*x[s-4] for s = t0-3..t0-1 -> slots 1,2,3.
        nh[0] = 0.0f;                        // overwritten before first read
        nh[1] = xh[5] * xh[1];
        nh[2] = xh[6] * xh[2];
        nh[3] = xh[7] * xh[3];
    }

    for (int tb = 0; tb < CH; tb += 8) {
        // ---- front-batch the 8 independent row loads (MLP = 8) ----
        float xv[8];
#pragma unroll
        for (int k = 0; k < 8; k++)
            xv[k] = xp[(long)(t0 + tb + k) * n];

        // ---- compute + store the 8 rows ----
#pragma unroll
        for (int k = 0; k < 8; k++) {
            const int t = t0 + tb + k;       // t % 8 == k
            const float4 cv = cc[t];

            const int i8 = k;                // x[t-8] slot (then receives x[t])
            const int i4 = (k + 4) & 7;      // x[t-4]
            const int j0 = k & 3;            // n1[t] destination
            const int j1 = (k + 3) & 3;      // n1[t-1]
            const int j2 = (k + 2) & 3;      // n1[t-2]
            const int j3 = (k + 1) & 3;      // n1[t-3]

            const float n1  = xv[k] * xh[i4];
            const float n2v = 1.0f - n1  * cv.x;
            const float n3  = 1.0f - n2v * (cv.y * nh[j1]);
            const float n4v = 1.0f - n3  * (cv.z * nh[j2]);
            const float n5  = 1.0f - n4v * (cv.w * nh[j3]);
            const float ov  = n5 * xh[i8];
            xh[i8] = xv[k];
            nh[j0] = n1;

            op[(long)t * n] = ov;
        }
    }
}

extern "C" void kernel_launch(void* const* d_in, const int* in_sizes, int n_in,
                              void* d_out, int out_size)
{
    const float* x  = (const float*)d_in[0];
    const float* c2 = (const float*)d_in[1];
    const float* c3 = (const float*)d_in[2];
    const float* c4 = (const float*)d_in[3];
    const float* c5 = (const float*)d_in[4];

    const int T = in_sizes[1];            // 256
    const int N = in_sizes[0] / T;        // 262144

    const int threads = 256;
    dim3 grid((N + threads - 1) / threads, T / CH);
    tanhP1_kernel<<<grid, threads>>>(x, c2, c3, c4, c5, (float*)d_out, N);
}

// round 7
// speedup vs baseline: 1.0245x; 1.0245x over previous
#include <cuda_runtime.h>

// tanhP1 bitstream stencil — R3 structure (float2 + CH=64 chunking + MLP=8),
// with chunk-interleaved block ordering.
// out[t] = n5 * x[t-8]:
//   n1 = x[t]*x[t-4]
//   n2 = 1 - n1*c2[t]
//   n3 = 1 - n2*c3[t]*n1[t-1]
//   n4 = 1 - n3*c4[t]*n1[t-2]
//   n5 = 1 - n4*c5[t]*n1[t-3]
// Exact {0,1} floats -> FFMA arithmetic is bit-exact.
//
// Round-7 rationale:
//  * R3 (float2 x CH=64 x batched loads) is the proven best: 6.11 TB/s.
//    Scalar (R6) and unchunked (R4/R5) variants all sat at 5.55-5.68 TB/s
//    regardless of occupancy -> revert to R3 exactly.
//  * ONE change: blockIdx.x = chunk index (fastest-varying) so every
//    scheduling wave contains all 4 t-chunks -> 4 decorrelated DRAM streams
//    live from launch, instead of streams coming online serially.

#define TT 256
#define CH 64          // chunk length (multiple of 8)

__global__ __launch_bounds__(256)
void tanhP1_kernel(const float2* __restrict__ x,
                   const float*  __restrict__ c2,
                   const float*  __restrict__ c3,
                   const float*  __restrict__ c4,
                   const float*  __restrict__ c5,
                   float2* __restrict__ out,
                   int n2)   // N/2 float2 columns
{
    __shared__ float4 cc[TT];
    for (int i = threadIdx.x; i < TT; i += blockDim.x)
        cc[i] = make_float4(c2[i], c3[i], c4[i], c5[i]);
    __syncthreads();

    // Chunk index varies FASTEST across blocks (grid.x = T/CH).
    const int col = blockIdx.y * blockDim.x + threadIdx.x;
    if (col >= n2) return;
    const int t0 = blockIdx.x * CH;          // multiple of 8

    const float2* xp = x + col;
    float2*       op = out + col;

    // Delay lines: x at time s lives in slot s&7; n1 at time s in slot s&3.
    float xh[8][2];
    float nh[4][2];

    if (t0 == 0) {
#pragma unroll
        for (int i = 0; i < 8; i++) { xh[i][0] = 0.0f; xh[i][1] = 0.0f; }
#pragma unroll
        for (int i = 0; i < 4; i++) { nh[i][0] = 0.0f; nh[i][1] = 0.0f; }
    } else {
        // Halo rows t0-8..t0-1 land in slots 0..7 (t0 % 8 == 0).
        float2 hv[8];
#pragma unroll
        for (int k = 0; k < 8; k++)
            hv[k] = xp[(long)(t0 - 8 + k) * n2];
#pragma unroll
        for (int k = 0; k < 8; k++) { xh[k][0] = hv[k].x; xh[k][1] = hv[k].y; }
        // n1[s] = x[s]*x[s-4] for s = t0-3..t0-1 -> slots 1,2,3.
#pragma unroll
        for (int l = 0; l < 2; l++) {
            nh[0][l] = 0.0f;                    // overwritten before first read
            nh[1][l] = xh[5][l] * xh[1][l];
            nh[2][l] = xh[6][l] * xh[2][l];
            nh[3][l] = xh[7][l] * xh[3][l];
        }
    }

    for (int tb = 0; tb < CH; tb += 8) {
        // ---- front-batch the 8 independent row loads (MLP = 8) ----
        float2 xv[8];
#pragma unroll
        for (int k = 0; k < 8; k++)
            xv[k] = xp[(long)(t0 + tb + k) * n2];

        // ---- compute + store the 8 rows ----
#pragma unroll
        for (int k = 0; k < 8; k++) {
            const int t = t0 + tb + k;       // t % 8 == k
            const float4 cv = cc[t];

            const int i8 = k;                // x[t-8] slot (then receives x[t])
            const int i4 = (k + 4) & 7;      // x[t-4]
            const int j0 = k & 3;            // n1[t] destination
            const int j1 = (k + 3) & 3;      // n1[t-1]
            const int j2 = (k + 2) & 3;      // n1[t-2]
            const int j3 = (k + 1) & 3;      // n1[t-3]

            float xt[2] = {xv[k].x, xv[k].y};
            float ov[2];
#pragma unroll
            for (int l = 0; l < 2; l++) {
                const float n1  = xt[l] * xh[i4][l];
                const float n2v = 1.0f - n1  * cv.x;
                const float n3  = 1.0f - n2v * (cv.y * nh[j1][l]);
                const float n4v = 1.0f - n3  * (cv.z * nh[j2][l]);
                const float n5  = 1.0f - n4v * (cv.w * nh[j3][l]);
                ov[l] = n5 * xh[i8][l];
                xh[i8][l] = xt[l];
                nh[j0][l] = n1;
            }
            op[(long)t * n2] = make_float2(ov[0], ov[1]);
        }
    }
}

extern "C" void kernel_launch(void* const* d_in, const int* in_sizes, int n_in,
                              void* d_out, int out_size)
{
    const float* x  = (const float*)d_in[0];
    const float* c2 = (const float*)d_in[1];
    const float* c3 = (const float*)d_in[2];
    const float* c4 = (const float*)d_in[3];
    const float* c5 = (const float*)d_in[4];

    const int T  = in_sizes[1];           // 256
    const int N  = in_sizes[0] / T;       // 262144
    const int n2 = N / 2;                 // float2 columns

    const int threads = 256;
    dim3 grid(T / CH, (n2 + threads - 1) / threads);   // chunk fastest
    tanhP1_kernel<<<grid, threads>>>((const float2*)x, c2, c3, c4, c5,
                                     (float2*)d_out, n2);
}